// round 10
// baseline (speedup 1.0000x reference)
#include <cuda_runtime.h>
#include <cuda_bf16.h>

// Problem shape (fixed by reference setup_inputs): B=8, N=8192, D=512.
// out[b, n]     = dot(s_bn, h_rl_bn) / (max(||s||,eps) * max(||h_rl||,eps))
// out[b, N + n] = dot(s_bn, h_fk_bn) / (max(||s||,eps) * max(||h_fk||,eps))
//
// Pure streaming workload: 402MB compulsory reads -> LTS-cap bound (~6.5TB/s
// measured). This round: persistent warps with SOFTWARE PREFETCH double
// buffering. R3 showed naive grid-stride serializes (next row's loads wait
// behind the shuffle-reduction tail); here row i+1's 12 LDG.128 are issued
// BEFORE row i's reduction, so each warp keeps loads in flight continuously
// and DRAM duty-cycle gaps (the 18% idle) close. 2 CTAs x 256 thr per SM,
// 128-reg budget fits both 48-reg float4 buffers without spills.

#define D_DIM  512
#define N_DIM  8192          // power of two -> row/N is a shift
#define EPS    1e-12f

__device__ __forceinline__ void load_row(const float* __restrict__ s,
                                         const float* __restrict__ h_rl,
                                         const float* __restrict__ h_fk,
                                         int row, int lane,
                                         float4 (&av)[4], float4 (&rv)[4], float4 (&fv)[4])
{
    const size_t base = (size_t)row * D_DIM;
    const float4* __restrict__ s4 = (const float4*)(s    + base);
    const float4* __restrict__ r4 = (const float4*)(h_rl + base);
    const float4* __restrict__ f4 = (const float4*)(h_fk + base);
    #pragma unroll
    for (int i = 0; i < 4; i++) av[i] = __ldcs(&s4[lane + i * 32]);
    #pragma unroll
    for (int i = 0; i < 4; i++) rv[i] = __ldcs(&r4[lane + i * 32]);
    #pragma unroll
    for (int i = 0; i < 4; i++) fv[i] = __ldcs(&f4[lane + i * 32]);
}

__device__ __forceinline__ void process_row(const float4 (&av)[4],
                                            const float4 (&rv)[4],
                                            const float4 (&fv)[4],
                                            int row, int lane,
                                            float* __restrict__ out)
{
    float ss = 0.f, rr = 0.f, ff = 0.f, sr = 0.f, sf = 0.f;

    #pragma unroll
    for (int i = 0; i < 4; i++) {
        const float4 a = av[i], r = rv[i], f = fv[i];
        ss = fmaf(a.x, a.x, ss); ss = fmaf(a.y, a.y, ss);
        ss = fmaf(a.z, a.z, ss); ss = fmaf(a.w, a.w, ss);
        rr = fmaf(r.x, r.x, rr); rr = fmaf(r.y, r.y, rr);
        rr = fmaf(r.z, r.z, rr); rr = fmaf(r.w, r.w, rr);
        ff = fmaf(f.x, f.x, ff); ff = fmaf(f.y, f.y, ff);
        ff = fmaf(f.z, f.z, ff); ff = fmaf(f.w, f.w, ff);
        sr = fmaf(a.x, r.x, sr); sr = fmaf(a.y, r.y, sr);
        sr = fmaf(a.z, r.z, sr); sr = fmaf(a.w, r.w, sr);
        sf = fmaf(a.x, f.x, sf); sf = fmaf(a.y, f.y, sf);
        sf = fmaf(a.z, f.z, sf); sf = fmaf(a.w, f.w, sf);
    }

    #pragma unroll
    for (int off = 16; off > 0; off >>= 1) {
        ss += __shfl_xor_sync(0xFFFFFFFFu, ss, off);
        rr += __shfl_xor_sync(0xFFFFFFFFu, rr, off);
        ff += __shfl_xor_sync(0xFFFFFFFFu, ff, off);
        sr += __shfl_xor_sync(0xFFFFFFFFu, sr, off);
        sf += __shfl_xor_sync(0xFFFFFFFFu, sf, off);
    }

    if (lane == 0) {
        const float ns = fmaxf(sqrtf(ss), EPS);
        const float nr = fmaxf(sqrtf(rr), EPS);
        const float nf = fmaxf(sqrtf(ff), EPS);
        const int b = row >> 13;             // row / 8192
        const int n = row & (N_DIM - 1);     // row % 8192
        float* ob = out + (size_t)b * (2 * N_DIM);
        __stcs(&ob[n],         sr / (ns * nr));
        __stcs(&ob[N_DIM + n], sf / (ns * nf));
    }
}

__global__ __launch_bounds__(256, 2)
void cosine_rows_pipe_kernel(const float* __restrict__ s,
                             const float* __restrict__ h_rl,
                             const float* __restrict__ h_fk,
                             float* __restrict__ out,
                             int n_rows)
{
    const int warps_per_block = blockDim.x >> 5;
    const int stride = gridDim.x * warps_per_block;
    int row = blockIdx.x * warps_per_block + (threadIdx.x >> 5);
    const int lane = threadIdx.x & 31;

    if (row >= n_rows) return;

    float4 a0[4], r0[4], f0[4];
    float4 a1[4], r1[4], f1[4];

    // Prologue: buffer 0 holds the first row.
    load_row(s, h_rl, h_fk, row, lane, a0, r0, f0);

    while (true) {
        // --- phase 0: prefetch next into buf1, then reduce buf0 ---
        int next = row + stride;
        if (next < n_rows)
            load_row(s, h_rl, h_fk, next, lane, a1, r1, f1);
        process_row(a0, r0, f0, row, lane, out);
        if (next >= n_rows) break;
        row = next;

        // --- phase 1: prefetch next into buf0, then reduce buf1 ---
        next = row + stride;
        if (next < n_rows)
            load_row(s, h_rl, h_fk, next, lane, a0, r0, f0);
        process_row(a1, r1, f1, row, lane, out);
        if (next >= n_rows) break;
        row = next;
    }
}

extern "C" void kernel_launch(void* const* d_in, const int* in_sizes, int n_in,
                              void* d_out, int out_size)
{
    const float* s    = (const float*)d_in[0];
    const float* h_rl = (const float*)d_in[1];
    const float* h_fk = (const float*)d_in[2];
    float* out = (float*)d_out;

    const int n_rows = in_sizes[0] / D_DIM;      // B*N = 65536

    const int threads = 256;                     // 8 warps per block
    const int blocks  = 152 * 2;                 // persistent: 2 CTAs per SM (GB300: 152 SMs)
    cosine_rows_pipe_kernel<<<blocks, threads>>>(s, h_rl, h_fk, out, n_rows);
}

// round 11
// speedup vs baseline: 1.0468x; 1.0468x over previous
#include <cuda_runtime.h>
#include <cuda_bf16.h>

// Problem shape (fixed by reference setup_inputs): B=8, N=8192, D=512.
// out[b, n]     = dot(s_bn, h_rl_bn) / (max(||s||,eps) * max(||h_rl||,eps))
// out[b, N + n] = dot(s_bn, h_fk_bn) / (max(||s||,eps) * max(||h_fk||,eps))
//
// Pure streaming: 402MB compulsory reads -> LTS-cap bound (~6.7TB/s measured).
// Structure distilled from R1-R9 measurements:
//  - front-batched LDG.128 bursts beat loop-carried prefetch (no branch gating,
//    no tail imbalance),
//  - TWO adjacent rows per warp -> 24 independent LDG.128 in flight per lane
//    before any reduction (row 1's loads issue before row 0's shuffle wall,
//    capturing the R9 prefetch win without the persistent loop),
//  - evict-first (.cs) loads/stores, warp retirement supplies continuity.

#define D_DIM  512
#define N_DIM  8192          // power of two -> row/N is a shift
#define EPS    1e-12f

__device__ __forceinline__ void reduce_and_store(float4 (&av)[4], float4 (&rv)[4],
                                                 float4 (&fv)[4],
                                                 int row, int lane,
                                                 float* __restrict__ out)
{
    float ss = 0.f, rr = 0.f, ff = 0.f, sr = 0.f, sf = 0.f;

    #pragma unroll
    for (int i = 0; i < 4; i++) {
        const float4 a = av[i], r = rv[i], f = fv[i];
        ss = fmaf(a.x, a.x, ss); ss = fmaf(a.y, a.y, ss);
        ss = fmaf(a.z, a.z, ss); ss = fmaf(a.w, a.w, ss);
        rr = fmaf(r.x, r.x, rr); rr = fmaf(r.y, r.y, rr);
        rr = fmaf(r.z, r.z, rr); rr = fmaf(r.w, r.w, rr);
        ff = fmaf(f.x, f.x, ff); ff = fmaf(f.y, f.y, ff);
        ff = fmaf(f.z, f.z, ff); ff = fmaf(f.w, f.w, ff);
        sr = fmaf(a.x, r.x, sr); sr = fmaf(a.y, r.y, sr);
        sr = fmaf(a.z, r.z, sr); sr = fmaf(a.w, r.w, sr);
        sf = fmaf(a.x, f.x, sf); sf = fmaf(a.y, f.y, sf);
        sf = fmaf(a.z, f.z, sf); sf = fmaf(a.w, f.w, sf);
    }

    #pragma unroll
    for (int off = 16; off > 0; off >>= 1) {
        ss += __shfl_xor_sync(0xFFFFFFFFu, ss, off);
        rr += __shfl_xor_sync(0xFFFFFFFFu, rr, off);
        ff += __shfl_xor_sync(0xFFFFFFFFu, ff, off);
        sr += __shfl_xor_sync(0xFFFFFFFFu, sr, off);
        sf += __shfl_xor_sync(0xFFFFFFFFu, sf, off);
    }

    if (lane == 0) {
        const float ns = fmaxf(sqrtf(ss), EPS);
        const float nr = fmaxf(sqrtf(rr), EPS);
        const float nf = fmaxf(sqrtf(ff), EPS);
        const int b = row >> 13;             // row / 8192
        const int n = row & (N_DIM - 1);     // row % 8192
        float* ob = out + (size_t)b * (2 * N_DIM);
        __stcs(&ob[n],         sr / (ns * nr));
        __stcs(&ob[N_DIM + n], sf / (ns * nf));
    }
}

__global__ __launch_bounds__(256, 2)
void cosine_rows2_kernel(const float* __restrict__ s,
                         const float* __restrict__ h_rl,
                         const float* __restrict__ h_fk,
                         float* __restrict__ out,
                         int n_rows)
{
    const int warps_per_block = blockDim.x >> 5;
    const int warp = blockIdx.x * warps_per_block + (threadIdx.x >> 5);
    const int lane = threadIdx.x & 31;

    const int row0 = warp * 2;
    const int row1 = row0 + 1;
    if (row0 >= n_rows) return;

    const size_t base0 = (size_t)row0 * D_DIM;
    const float4* __restrict__ s40 = (const float4*)(s    + base0);
    const float4* __restrict__ r40 = (const float4*)(h_rl + base0);
    const float4* __restrict__ f40 = (const float4*)(h_fk + base0);
    // row1 = row0+1 -> its data is the next 2KB; separate pointers keep
    // the address math trivially independent for the load batch.
    const float4* __restrict__ s41 = s40 + (D_DIM / 4);
    const float4* __restrict__ r41 = r40 + (D_DIM / 4);
    const float4* __restrict__ f41 = f40 + (D_DIM / 4);

    const bool have1 = (row1 < n_rows);

    // Front-batch ALL 24 loads (12 per row) before any reduction.
    float4 a0[4], r0[4], f0[4], a1[4], r1[4], f1[4];
    #pragma unroll
    for (int i = 0; i < 4; i++) a0[i] = __ldcs(&s40[lane + i * 32]);
    #pragma unroll
    for (int i = 0; i < 4; i++) r0[i] = __ldcs(&r40[lane + i * 32]);
    #pragma unroll
    for (int i = 0; i < 4; i++) f0[i] = __ldcs(&f40[lane + i * 32]);
    if (have1) {
        #pragma unroll
        for (int i = 0; i < 4; i++) a1[i] = __ldcs(&s41[lane + i * 32]);
        #pragma unroll
        for (int i = 0; i < 4; i++) r1[i] = __ldcs(&r41[lane + i * 32]);
        #pragma unroll
        for (int i = 0; i < 4; i++) f1[i] = __ldcs(&f41[lane + i * 32]);
    }

    reduce_and_store(a0, r0, f0, row0, lane, out);
    if (have1)
        reduce_and_store(a1, r1, f1, row1, lane, out);
}

extern "C" void kernel_launch(void* const* d_in, const int* in_sizes, int n_in,
                              void* d_out, int out_size)
{
    const float* s    = (const float*)d_in[0];
    const float* h_rl = (const float*)d_in[1];
    const float* h_fk = (const float*)d_in[2];
    float* out = (float*)d_out;

    const int n_rows = in_sizes[0] / D_DIM;      // B*N = 65536

    const int threads = 256;                     // 8 warps -> 16 rows per block
    const int rows_per_block = 16;
    const int blocks = (n_rows + rows_per_block - 1) / rows_per_block;  // 4096
    cosine_rows2_kernel<<<blocks, threads>>>(s, h_rl, h_fk, out, n_rows);
}